// round 1
// baseline (speedup 1.0000x reference)
#include <cuda_runtime.h>
#include <cstdint>

#define N_NODES 16384
#define KNN 10

// ---------------- scratch (static device allocations; no runtime alloc) ----------------
__device__ float d_E [N_NODES * 192];
__device__ float d_H [N_NODES * 128];
__device__ float d_g1[N_NODES * 64];
__device__ float d_g2[N_NODES * 64];
__device__ float d_P [N_NODES * 64];
__device__ float d_Qm[N_NODES * 64];
__device__ float d_sqn[N_NODES];
__device__ int   d_idx[N_NODES * KNN];
__device__ float d_WP[128 * 64];
__device__ float d_WQ[128 * 64];

// ---------------- stage 1: per-modality embeds (relu) -> E[N,192] ----------------
__global__ void embed_kernel(const float* __restrict__ nf, const float* __restrict__ rf,
                             const float* __restrict__ tf,
                             const float* __restrict__ Wb, const float* __restrict__ bb,
                             const float* __restrict__ Wr, const float* __restrict__ br,
                             const float* __restrict__ Wt, const float* __restrict__ bt)
{
    __shared__ float s[136];   // 8 node feats, 64 rf, 64 txp
    const int n = blockIdx.x;
    const int t = threadIdx.x;
    if (t < 8)                 s[t]            = nf[n * 8 + t];
    if (t >= 64 && t < 128)    s[8 + (t - 64)] = rf[n * 64 + (t - 64)];
    if (t >= 128)              s[72 + (t-128)] = tf[n * 64 + (t - 128)];
    __syncthreads();

    float acc;
    if (t < 64) {
        acc = bb[t];
        #pragma unroll
        for (int e = 0; e < 8; e++) acc = fmaf(s[e], Wb[e * 64 + t], acc);
    } else if (t < 128) {
        const int o = t - 64;
        acc = br[o];
        #pragma unroll 8
        for (int e = 0; e < 64; e++) acc = fmaf(s[8 + e], Wr[e * 64 + o], acc);
    } else {
        const int o = t - 128;
        acc = bt[o];
        #pragma unroll 8
        for (int e = 0; e < 64; e++) acc = fmaf(s[72 + e], Wt[e * 64 + o], acc);
    }
    d_E[n * 192 + t] = fmaxf(acc, 0.0f);
}

// ---------------- generic tiled fp32 GEMM: C[M,Nc] = act(A[M,Kd] @ W[Kd,Nc] + bias) ----
// BM=BN=64, BK=16, 256 threads, 4x4 microtile. M from gridDim.x*64, Nc from gridDim.y*64.
// ACT: 0 = none, 2 = leaky_relu(0.01)
template <int ACT>
__global__ __launch_bounds__(256) void gemm_kernel(const float* __restrict__ A,
                                                   const float* __restrict__ W,
                                                   const float* __restrict__ bias,
                                                   float* __restrict__ C,
                                                   int Kd, int Nc)
{
    __shared__ float As[16][64];
    __shared__ float Ws[16][64];
    const int m0 = blockIdx.x * 64;
    const int n0 = blockIdx.y * 64;
    const int tid = threadIdx.x;
    const int tx = tid & 15;
    const int ty = tid >> 4;

    float acc[4][4];
    #pragma unroll
    for (int i = 0; i < 4; i++)
        #pragma unroll
        for (int j = 0; j < 4; j++) acc[i][j] = 0.0f;

    for (int k0 = 0; k0 < Kd; k0 += 16) {
        {   // A tile: 64x16
            const int m  = tid >> 2;
            const int kq = (tid & 3) * 4;
            float4 v = *reinterpret_cast<const float4*>(&A[(m0 + m) * Kd + k0 + kq]);
            As[kq + 0][m] = v.x; As[kq + 1][m] = v.y;
            As[kq + 2][m] = v.z; As[kq + 3][m] = v.w;
            // W tile: 16x64
            const int kk = tid >> 4;
            const int nq = (tid & 15) * 4;
            float4 w = *reinterpret_cast<const float4*>(&W[(k0 + kk) * Nc + n0 + nq]);
            *reinterpret_cast<float4*>(&Ws[kk][nq]) = w;
        }
        __syncthreads();
        #pragma unroll
        for (int k = 0; k < 16; k++) {
            float4 a = *reinterpret_cast<const float4*>(&As[k][ty * 4]);
            float4 b = *reinterpret_cast<const float4*>(&Ws[k][tx * 4]);
            float av[4] = {a.x, a.y, a.z, a.w};
            float bv[4] = {b.x, b.y, b.z, b.w};
            #pragma unroll
            for (int i = 0; i < 4; i++)
                #pragma unroll
                for (int j = 0; j < 4; j++)
                    acc[i][j] = fmaf(av[i], bv[j], acc[i][j]);
        }
        __syncthreads();
    }

    #pragma unroll
    for (int i = 0; i < 4; i++) {
        const int m = m0 + ty * 4 + i;
        #pragma unroll
        for (int j = 0; j < 4; j++) {
            const int n = n0 + tx * 4 + j;
            float v = acc[i][j] + (bias ? bias[n] : 0.0f);
            if (ACT == 2) v = (v > 0.0f) ? v : 0.01f * v;
            C[m * Nc + n] = v;
        }
    }
}

// ---------------- squared norms ----------------
__global__ void sqnorm_kernel(const float* __restrict__ X, float* __restrict__ out, int D)
{
    const int n    = blockIdx.x * 8 + (threadIdx.x >> 5);
    const int lane = threadIdx.x & 31;
    float s = 0.0f;
    for (int d = lane; d < D; d += 32) { float v = X[n * D + d]; s = fmaf(v, v, s); }
    #pragma unroll
    for (int o = 16; o > 0; o >>= 1) s += __shfl_xor_sync(0xFFFFFFFFu, s, o);
    if (lane == 0) out[n] = s;
}

// ---------------- top-k insert helper (fully unrolled, register-resident) ----------------
__device__ __forceinline__ void topk_insert(float (&topd)[KNN], int (&topi)[KNN],
                                            float dd, int ci)
{
    topd[KNN - 1] = dd; topi[KNN - 1] = ci;
    #pragma unroll
    for (int z = KNN - 2; z >= 0; z--) {
        if (topd[z] > topd[z + 1]) {
            float td = topd[z]; topd[z] = topd[z + 1]; topd[z + 1] = td;
            int   ti = topi[z]; topi[z] = topi[z + 1]; topi[z + 1] = ti;
        }
    }
}

// ---------------- fused KNN: Gram tile GEMM + running top-10 ----------------
// 128 queries per block, 128-candidate tiles, 256 threads, 8x8 microtiles.
// smem: qt[D][128] (transposed queries), scr = union{ ct[D][128], dist[128][132], merge }
template <int D>
__global__ __launch_bounds__(256, 1) void knn_kernel(const float* __restrict__ X,
                                                     const float* __restrict__ sqn,
                                                     int* __restrict__ outIdx)
{
    extern __shared__ float sm[];
    float* qt  = sm;             // D*128 floats
    float* scr = sm + D * 128;   // 16896 floats (>= max(D*128, 128*132))
    __shared__ float sqq[128];
    __shared__ float sqc[128];

    const int tid = threadIdx.x;
    const int q0  = blockIdx.x * 128;
    const int tx  = tid & 15;
    const int ty  = tid >> 4;

    // load query tile transposed: qt[d][q]
    for (int i = tid; i < 128 * (D / 4); i += 256) {
        const int q  = i / (D / 4);
        const int dq = (i % (D / 4)) * 4;
        float4 v = *reinterpret_cast<const float4*>(&X[(q0 + q) * D + dq]);
        qt[(dq + 0) * 128 + q] = v.x; qt[(dq + 1) * 128 + q] = v.y;
        qt[(dq + 2) * 128 + q] = v.z; qt[(dq + 3) * 128 + q] = v.w;
    }
    if (tid < 128) sqq[tid] = sqn[q0 + tid];

    float topd[KNN]; int topi[KNN];
    #pragma unroll
    for (int i = 0; i < KNN; i++) { topd[i] = 1e30f; topi[i] = 0; }

    const int qmine = tid & 127;        // query owned for scanning
    const int cbase = (tid >> 7) * 64;  // half of the candidate tile

    for (int c0 = 0; c0 < N_NODES; c0 += 128) {
        __syncthreads();   // previous scan done before scr is overwritten
        // load candidate tile transposed into scr: ct[d][c]
        for (int i = tid; i < 128 * (D / 4); i += 256) {
            const int c  = i / (D / 4);
            const int dq = (i % (D / 4)) * 4;
            float4 v = *reinterpret_cast<const float4*>(&X[(c0 + c) * D + dq]);
            scr[(dq + 0) * 128 + c] = v.x; scr[(dq + 1) * 128 + c] = v.y;
            scr[(dq + 2) * 128 + c] = v.z; scr[(dq + 3) * 128 + c] = v.w;
        }
        if (tid < 128) sqc[tid] = sqn[c0 + tid];
        __syncthreads();

        float acc[8][8];
        #pragma unroll
        for (int i = 0; i < 8; i++)
            #pragma unroll
            for (int j = 0; j < 8; j++) acc[i][j] = 0.0f;

        #pragma unroll 4
        for (int k = 0; k < D; k++) {
            float4 a0 = *reinterpret_cast<const float4*>(&qt[k * 128 + ty * 8]);
            float4 a1 = *reinterpret_cast<const float4*>(&qt[k * 128 + ty * 8 + 4]);
            float4 b0 = *reinterpret_cast<const float4*>(&scr[k * 128 + tx * 8]);
            float4 b1 = *reinterpret_cast<const float4*>(&scr[k * 128 + tx * 8 + 4]);
            float av[8] = {a0.x, a0.y, a0.z, a0.w, a1.x, a1.y, a1.z, a1.w};
            float bv[8] = {b0.x, b0.y, b0.z, b0.w, b1.x, b1.y, b1.z, b1.w};
            #pragma unroll
            for (int i = 0; i < 8; i++)
                #pragma unroll
                for (int j = 0; j < 8; j++)
                    acc[i][j] = fmaf(av[i], bv[j], acc[i][j]);
        }
        __syncthreads();   // done reading scr as ct

        // distances into scr as dist[q][132] (pitch 132 kills 32-way conflicts on scan)
        #pragma unroll
        for (int i = 0; i < 8; i++) {
            const int q = ty * 8 + i;
            #pragma unroll
            for (int j = 0; j < 8; j++) {
                const int c = tx * 8 + j;
                float dd = sqq[q] + sqc[c] - 2.0f * acc[i][j];
                if (q0 + q == c0 + c) dd = 1e30f;   // exclude self
                scr[q * 132 + c] = dd;
            }
        }
        __syncthreads();

        // scan: 2 threads per query, 64 candidates each
        #pragma unroll 4
        for (int cc = 0; cc < 64; cc++) {
            const float dd = scr[qmine * 132 + cbase + cc];
            if (dd < topd[KNN - 1]) topk_insert(topd, topi, dd, c0 + cbase + cc);
        }
    }

    // merge the two per-query halves
    __syncthreads();
    if (tid >= 128) {
        const int q = tid - 128;
        #pragma unroll
        for (int i = 0; i < KNN; i++) {
            scr[q * 2 * KNN + i] = topd[i];
            reinterpret_cast<int*>(scr)[q * 2 * KNN + KNN + i] = topi[i];
        }
    }
    __syncthreads();
    if (tid < 128) {
        #pragma unroll
        for (int i = 0; i < KNN; i++) {
            const float dd = scr[tid * 2 * KNN + i];
            const int   ci = reinterpret_cast<int*>(scr)[tid * 2 * KNN + KNN + i];
            if (dd < topd[KNN - 1]) topk_insert(topd, topi, dd, ci);
        }
        #pragma unroll
        for (int i = 0; i < KNN; i++) outIdx[(q0 + tid) * KNN + i] = topi[i];
    }
}

// ---------------- EdgeConv weight split: WP = Wa - Wb, WQ = Wb ----------------
__global__ void prepw_kernel(const float* __restrict__ We, int D)
{
    const int i = blockIdx.x * 256 + threadIdx.x;
    if (i < D * 64) {
        const float b = We[D * 64 + i];
        d_WQ[i] = b;
        d_WP[i] = We[i] - b;
    }
}

// ---------------- EdgeConv aggregation: g[n,o] = max_k leaky(P[n,o] + Q[idx[n,k],o]) ----
__global__ void maxagg_kernel(const float* __restrict__ P, const float* __restrict__ Q,
                              const int* __restrict__ idx, float* __restrict__ g)
{
    const int tid = threadIdx.x;
    const int n = blockIdx.x * 4 + (tid >> 6);
    const int o = tid & 63;
    const float p = P[n * 64 + o];
    float m = -1e30f;
    #pragma unroll
    for (int kk = 0; kk < KNN; kk++) {
        const int j = idx[n * KNN + kk];
        float v = p + Q[j * 64 + o];
        v = (v > 0.0f) ? v : 0.01f * v;
        m = fmaxf(m, v);
    }
    g[n * 64 + o] = m;
}

// ---------------- classifier: logits = [g1,g2] @ Wc + bc ----------------
__global__ void classifier_kernel(const float* __restrict__ Wc, const float* __restrict__ bc,
                                  float* __restrict__ out)
{
    const int tid = threadIdx.x;
    const int n = blockIdx.x * 16 + (tid >> 4);
    const int c = tid & 15;
    float acc = bc[c];
    const float* g1r = d_g1 + n * 64;
    const float* g2r = d_g2 + n * 64;
    #pragma unroll 8
    for (int o = 0; o < 64; o++) {
        acc = fmaf(g1r[o], Wc[o * 16 + c], acc);
        acc = fmaf(g2r[o], Wc[(64 + o) * 16 + c], acc);
    }
    out[n * 16 + c] = acc;
}

// ---------------- launch ----------------
extern "C" void kernel_launch(void* const* d_in, const int* in_sizes, int n_in,
                              void* d_out, int out_size)
{
    const float* node_feat = (const float*)d_in[0];
    const float* rf_feat   = (const float*)d_in[1];
    const float* txp_feat  = (const float*)d_in[2];
    const float* Wb  = (const float*)d_in[3];
    const float* bb  = (const float*)d_in[4];
    const float* Wr  = (const float*)d_in[5];
    const float* br  = (const float*)d_in[6];
    const float* Wt  = (const float*)d_in[7];
    const float* bt  = (const float*)d_in[8];
    const float* Wf  = (const float*)d_in[9];
    const float* bf  = (const float*)d_in[10];
    const float* We1 = (const float*)d_in[11];
    const float* be1 = (const float*)d_in[12];
    const float* We2 = (const float*)d_in[13];
    const float* be2 = (const float*)d_in[14];
    const float* Wc  = (const float*)d_in[15];
    const float* bc  = (const float*)d_in[16];
    float* out = (float*)d_out;

    void *pE, *pH, *pg1, *pg2, *pP, *pQ, *psqn, *pidx, *pWP, *pWQ;
    cudaGetSymbolAddress(&pE,   d_E);
    cudaGetSymbolAddress(&pH,   d_H);
    cudaGetSymbolAddress(&pg1,  d_g1);
    cudaGetSymbolAddress(&pg2,  d_g2);
    cudaGetSymbolAddress(&pP,   d_P);
    cudaGetSymbolAddress(&pQ,   d_Qm);
    cudaGetSymbolAddress(&psqn, d_sqn);
    cudaGetSymbolAddress(&pidx, d_idx);
    cudaGetSymbolAddress(&pWP,  d_WP);
    cudaGetSymbolAddress(&pWQ,  d_WQ);

    const int SCR = 16896;  // floats: max(128*132, D*128)
    const int smem1 = (128 * 128 + SCR) * 4;  // 133120 B
    const int smem2 = (64  * 128 + SCR) * 4;  // 100352 B
    cudaFuncSetAttribute(knn_kernel<128>, cudaFuncAttributeMaxDynamicSharedMemorySize, smem1);
    cudaFuncSetAttribute(knn_kernel<64>,  cudaFuncAttributeMaxDynamicSharedMemorySize, smem2);

    // stage 1: embeds + fusion
    embed_kernel<<<N_NODES, 192>>>(node_feat, rf_feat, txp_feat, Wb, bb, Wr, br, Wt, bt);
    gemm_kernel<2><<<dim3(N_NODES / 64, 2), 256>>>((const float*)pE, Wf, bf, (float*)pH, 192, 128);

    // EdgeConv 1
    sqnorm_kernel<<<N_NODES / 8, 256>>>((const float*)pH, (float*)psqn, 128);
    knn_kernel<128><<<128, 256, smem1>>>((const float*)pH, (const float*)psqn, (int*)pidx);
    prepw_kernel<<<(128 * 64 + 255) / 256, 256>>>(We1, 128);
    gemm_kernel<0><<<dim3(N_NODES / 64, 1), 256>>>((const float*)pH, (const float*)pWP, be1,
                                                   (float*)pP, 128, 64);
    gemm_kernel<0><<<dim3(N_NODES / 64, 1), 256>>>((const float*)pH, (const float*)pWQ, nullptr,
                                                   (float*)pQ, 128, 64);
    maxagg_kernel<<<N_NODES / 4, 256>>>((const float*)pP, (const float*)pQ,
                                        (const int*)pidx, (float*)pg1);

    // EdgeConv 2
    sqnorm_kernel<<<N_NODES / 8, 256>>>((const float*)pg1, (float*)psqn, 64);
    knn_kernel<64><<<128, 256, smem2>>>((const float*)pg1, (const float*)psqn, (int*)pidx);
    prepw_kernel<<<(64 * 64 + 255) / 256, 256>>>(We2, 64);
    gemm_kernel<0><<<dim3(N_NODES / 64, 1), 256>>>((const float*)pg1, (const float*)pWP, be2,
                                                   (float*)pP, 64, 64);
    gemm_kernel<0><<<dim3(N_NODES / 64, 1), 256>>>((const float*)pg1, (const float*)pWQ, nullptr,
                                                   (float*)pQ, 64, 64);
    maxagg_kernel<<<N_NODES / 4, 256>>>((const float*)pP, (const float*)pQ,
                                        (const int*)pidx, (float*)pg2);

    // classifier
    classifier_kernel<<<N_NODES / 16, 256>>>(Wc, bc, out);
}